// round 14
// baseline (speedup 1.0000x reference)
#include <cuda_runtime.h>

#define BATCH 1024
#define TT    70
#define EE    300      // input width per layer (E = 2H = 300)
#define HH    150
#define DEPTH 5
#define G4    600      // 4*H
#define NP    1200     // fw + bw gate-packed width
#define MROWS (BATCH*TT)

typedef unsigned long long u64;

// ---------------- device scratch (allocation-free) ----------------
__device__ float g_Wxp[DEPTH*EE*NP];      // packed x-weights  [l][k][dir*600 + u*4 + g]
__device__ float g_Whp[DEPTH*2*HH*G4];    // packed h-weights  [l][dir][k][u*4 + g]
__device__ float g_biasp[DEPTH*NP];       // packed bias
__device__ float g_xz[MROWS*NP];          // per-layer xz precompute (valid rows only)
__device__ float g_bufA[MROWS*EE];
__device__ float g_bufB[MROWS*EE];
__device__ int   g_lens[BATCH];
__device__ int   g_perm[BATCH];           // batches sorted by len desc (stable)
__device__ int   g_rows[MROWS];           // compacted valid (b,t) rows, sorted by (b,t)
__device__ int   g_nvalid;

// ---------------- f32x2 helpers ----------------
__device__ __forceinline__ u64 pack2(float x, float y) {
    u64 r; asm("mov.b64 %0, {%1, %2};" : "=l"(r) : "f"(x), "f"(y)); return r;
}
__device__ __forceinline__ void unpack2(u64 v, float& x, float& y) {
    asm("mov.b64 {%0, %1}, %2;" : "=f"(x), "=f"(y) : "l"(v));
}
__device__ __forceinline__ void fma2(u64& d, u64 a, u64 b) {
    asm("fma.rn.f32x2 %0, %1, %2, %0;" : "+l"(d) : "l"(a), "l"(b));
}

__device__ __forceinline__ float sigmf(float x) { return 1.0f / (1.0f + __expf(-x)); }
__device__ __forceinline__ float tanhfast(float x) { return 2.0f * sigmf(2.0f * x) - 1.0f; }

// ---------------- weight packing ----------------
__global__ void pack_weights(const float* __restrict__ fwk, const float* __restrict__ fwb,
                             const float* __restrict__ bwk, const float* __restrict__ bwb)
{
    int i = blockIdx.x * blockDim.x + threadIdx.x;
    int stride = gridDim.x * blockDim.x;
    // Wx part: rows 0..299 of kernel
    for (int idx = i; idx < DEPTH*EE*NP; idx += stride) {
        int l = idx / (EE*NP); int r = idx % (EE*NP);
        int k = r / NP; int cgl = r % NP;
        int dir = cgl / G4; int cc = cgl % G4;
        int u = cc >> 2; int g = cc & 3;
        const float* kk = dir ? bwk : fwk;
        g_Wxp[idx] = kk[(l*(EE+HH) + k)*G4 + u + HH*g];
    }
    // Wh part: rows 300..449 of kernel
    for (int idx = i; idx < DEPTH*2*HH*G4; idx += stride) {
        int l = idx / (2*HH*G4); int r = idx % (2*HH*G4);
        int dir = r / (HH*G4); int r2 = r % (HH*G4);
        int k = r2 / G4; int cc = r2 % G4;
        int u = cc >> 2; int g = cc & 3;
        const float* kk = dir ? bwk : fwk;
        g_Whp[idx] = kk[(l*(EE+HH) + EE + k)*G4 + u + HH*g];
    }
    for (int idx = i; idx < DEPTH*NP; idx += stride) {
        int l = idx / NP; int cgl = idx % NP;
        int dir = cgl / G4; int cc = cgl % G4;
        int u = cc >> 2; int g = cc & 3;
        g_biasp[idx] = (dir ? bwb : fwb)[l*G4 + u + HH*g];
    }
}

// ---------------- fused prep: lens + deterministic compaction + rank sort --------
// One block, 1024 threads (one per batch). ONE barrier; each thread independently
// computes its exclusive-prefix base and stable sort rank via broadcast LDS loops.
__global__ void __launch_bounds__(BATCH) prep_kernel(const int* __restrict__ mask)
{
    __shared__ int lensh[BATCH];
    const int b = threadIdx.x;

    int s = 0;
    #pragma unroll
    for (int t = 0; t < TT; t++) s += mask[b*TT + t];
    g_lens[b] = s;
    lensh[b] = s;
    __syncthreads();

    const int myl = s;
    int r = 0, base = 0;
    for (int i = 0; i < BATCH; i++) {
        int lb = lensh[i];
        r += (lb > myl) || (lb == myl && i < b);
        base += (i < b) ? lb : 0;
    }
    for (int t = 0; t < myl; t++) g_rows[base + t] = b*TT + t;
    g_perm[r] = b;
    if (b == BATCH - 1) g_nvalid = base + myl;
}

// ---------------- xz precompute GEMM over VALID rows: [nvalid,300] @ [300,1200] + bias ----
// BM=64, BN=128, BK=12, 128 threads, thread tile 8m x 8n, f32x2 packed along n.
// Register-prefetch double-buffer hides LDG latency under ~770 cyc of FMA work.
__global__ void __launch_bounds__(128) xz_gemm(int layer, int inSel, const float* __restrict__ Xin)
{
    const int nvalid = g_nvalid;
    const int bm = blockIdx.x * 64;
    if (bm >= nvalid) return;

    const float* A  = (inSel == 0) ? Xin : (inSel == 1 ? g_bufA : g_bufB);
    const float* Bw = g_Wxp + layer*EE*NP;
    const float* bias = g_biasp + layer*NP;
    float* C = g_xz;

    __shared__ __align__(16) float As[12][64];
    __shared__ __align__(16) float Bs[12][128];
    __shared__ int rowid[64];

    const int bn = blockIdx.y * 128;
    const int tid = threadIdx.x;
    const int tm = (tid >> 4) << 3;   // 0..56
    const int tn = (tid & 15) << 3;   // 0..120

    if (tid < 64) {
        int r = bm + tid;
        rowid[tid] = (r < nvalid) ? g_rows[r] : -1;
    }
    __syncthreads();

    // per-thread fixed load coordinates
    int am[6], ak[6];
    const float* aptr[6];
    #pragma unroll
    for (int i = 0; i < 6; i++) {
        int idx = tid + i*128;          // 0..767
        am[i] = idx / 12; ak[i] = idx % 12;
        int rr = rowid[am[i]];
        aptr[i] = A + (size_t)(rr < 0 ? 0 : rr)*EE + ak[i];
    }
    int bk[3], bn4[3]; bool bok[3];
    #pragma unroll
    for (int i = 0; i < 3; i++) {
        int idx = tid + i*128;          // 0..383
        bk[i] = idx >> 5; bn4[i] = (idx & 31) << 2;
        bok[i] = (bn + bn4[i] < NP);
    }

    u64 acc[8][4];
    #pragma unroll
    for (int i = 0; i < 8; i++)
        #pragma unroll
        for (int j = 0; j < 4; j++) acc[i][j] = 0ull;

    // prologue: fetch tile 0 into registers
    float  pa[6];
    float4 pb[3];
    #pragma unroll
    for (int i = 0; i < 6; i++) pa[i] = __ldg(aptr[i]);
    #pragma unroll
    for (int i = 0; i < 3; i++)
        pb[i] = bok[i] ? __ldg((const float4*)&Bw[bk[i]*NP + bn + bn4[i]])
                       : make_float4(0.f, 0.f, 0.f, 0.f);

    const int NTILE = EE / 12;   // 25
    for (int tno = 0; tno < NTILE; tno++) {
        #pragma unroll
        for (int i = 0; i < 6; i++) As[ak[i]][am[i]] = pa[i];
        #pragma unroll
        for (int i = 0; i < 3; i++) *(float4*)&Bs[bk[i]][bn4[i]] = pb[i];
        __syncthreads();

        if (tno + 1 < NTILE) {
            const int k0n = (tno + 1) * 12;
            #pragma unroll
            for (int i = 0; i < 6; i++) pa[i] = __ldg(aptr[i] + k0n);
            #pragma unroll
            for (int i = 0; i < 3; i++)
                pb[i] = bok[i] ? __ldg((const float4*)&Bw[(k0n + bk[i])*NP + bn + bn4[i]])
                               : make_float4(0.f, 0.f, 0.f, 0.f);
        }

        #pragma unroll
        for (int k = 0; k < 12; k++) {
            float4 a0 = *(const float4*)&As[k][tm];
            float4 a1 = *(const float4*)&As[k][tm + 4];
            u64 a[8];
            a[0] = pack2(a0.x, a0.x); a[1] = pack2(a0.y, a0.y);
            a[2] = pack2(a0.z, a0.z); a[3] = pack2(a0.w, a0.w);
            a[4] = pack2(a1.x, a1.x); a[5] = pack2(a1.y, a1.y);
            a[6] = pack2(a1.z, a1.z); a[7] = pack2(a1.w, a1.w);
            float4 b0 = *(const float4*)&Bs[k][tn];
            float4 b1 = *(const float4*)&Bs[k][tn + 4];
            u64 bb[4];
            bb[0] = pack2(b0.x, b0.y); bb[1] = pack2(b0.z, b0.w);
            bb[2] = pack2(b1.x, b1.y); bb[3] = pack2(b1.z, b1.w);
            #pragma unroll
            for (int i = 0; i < 8; i++)
                #pragma unroll
                for (int j = 0; j < 4; j++) fma2(acc[i][j], a[i], bb[j]);
        }
        __syncthreads();
    }
    // epilogue: add bias, scatter-store to absolute rows
    #pragma unroll
    for (int i = 0; i < 8; i++) {
        int rr = rowid[tm + i];
        if (rr < 0) continue;
        float* crow = C + (size_t)rr*NP + bn + tn;
        #pragma unroll
        for (int j = 0; j < 4; j++) {
            int col = bn + tn + 2*j;
            if (col < NP) {
                float lo, hi; unpack2(acc[i][j], lo, hi);
                lo += bias[col]; hi += bias[col + 1];
                float2 v = make_float2(lo, hi);
                *(float2*)(crow + 2*j) = v;
            }
        }
    }
}

// ---------------- recurrent kernel: ONE direction per block, 8 sorted batches ------
// grid (128, 2): blockIdx.y = direction. 320 threads = batch-half(2) x unit(160).
// 320-thread blocks cap registers at 204 -> ptxas can never be forced to spill
// (the 640-thread fused version forced a 102-reg cap right at our live count).
// Two blocks/SM restores the 640-thread/SM FMA load. xz gate loads prefetched
// before the dot product; no zero-fill (t>=len rows are never read downstream).
__global__ void __launch_bounds__(320) lstm_rec(int layer, int outSel)
{
    const int d = blockIdx.y;
    const float* xz  = g_xz;
    const float* Whp = g_Whp + (layer*2 + d)*HH*G4;
    float* outb = (outSel == 1) ? g_bufA : g_bufB;

    // double-buffered packed h: [buf][batch-pair][k], float2 = (b even, b odd)
    __shared__ __align__(16) float2 hsh[2][4][HH + 2];
    __shared__ int lensh[8];
    __shared__ int bidsh[8];

    const int tid = threadIdx.x;
    const int u   = tid % 160;
    const int bh  = tid / 160;       // 0..1 batch half
    const int bpb = bh * 2;
    const bool act = (u < HH);

    float c[4];
    #pragma unroll
    for (int b = 0; b < 4; b++) c[b] = 0.f;

    if (bh == 0 && act) {
        #pragma unroll
        for (int bp = 0; bp < 4; bp++) hsh[0][bp][u] = make_float2(0.f, 0.f);
    }
    if (tid < 8) {
        int bid = g_perm[blockIdx.x * 8 + tid];
        bidsh[tid] = bid;
        lensh[tid] = g_lens[bid];
    }
    __syncthreads();

    int len[4], bid[4];
    #pragma unroll
    for (int b = 0; b < 4; b++) { len[b] = lensh[bh*4 + b]; bid[b] = bidsh[bh*4 + b]; }
    const int mlen = max(max(len[0], len[1]), max(len[2], len[3]));
    const int blockMax = lensh[0];   // sorted desc

    const float* wp = Whp + u*4;
    const float* xzb[4];
    #pragma unroll
    for (int b = 0; b < 4; b++) xzb[b] = xz + (size_t)bid[b]*TT*NP + d*G4 + u*4;

    for (int s = 0; s < blockMax; s++) {
        const int rb = s & 1, wb = rb ^ 1;
        if (act && s < mlen) {
            // early xz gate prefetch: latency hides under the dot product below
            float4 xvp[4];
            int    tt[4];
            #pragma unroll
            for (int b = 0; b < 4; b++) {
                const bool v = (s < len[b]);
                const int t = (d == 0) ? s : (len[b] - 1 - s);
                tt[b] = t;
                xvp[b] = __ldg((const float4*)(xzb[b] + (size_t)(v ? t : 0)*NP));
            }

            u64 acc[2][4];
            #pragma unroll
            for (int bp = 0; bp < 2; bp++)
                #pragma unroll
                for (int g = 0; g < 4; g++) acc[bp][g] = 0ull;

            #pragma unroll 5
            for (int k = 0; k < HH; k += 2) {
                float4 w0 = __ldg((const float4*)(wp + k*G4));
                float4 w1 = __ldg((const float4*)(wp + (k+1)*G4));
                u64 wd0[4], wd1[4];
                wd0[0] = pack2(w0.x, w0.x); wd0[1] = pack2(w0.y, w0.y);
                wd0[2] = pack2(w0.z, w0.z); wd0[3] = pack2(w0.w, w0.w);
                wd1[0] = pack2(w1.x, w1.x); wd1[1] = pack2(w1.y, w1.y);
                wd1[2] = pack2(w1.z, w1.z); wd1[3] = pack2(w1.w, w1.w);
                #pragma unroll
                for (int bp = 0; bp < 2; bp++) {
                    const u64* hp = (const u64*)&hsh[rb][bpb + bp][k];
                    u64 h0 = hp[0], h1 = hp[1];
                    #pragma unroll
                    for (int g = 0; g < 4; g++) {
                        fma2(acc[bp][g], h0, wd0[g]);
                        fma2(acc[bp][g], h1, wd1[g]);
                    }
                }
            }
            // epilogue per batch pair
            #pragma unroll
            for (int bp = 0; bp < 2; bp++) {
                float zlo[4], zhi[4];
                #pragma unroll
                for (int g = 0; g < 4; g++) unpack2(acc[bp][g], zlo[g], zhi[g]);
                float2 hold = hsh[rb][bpb + bp][u];
                float hnew0 = 0.f, hnew1 = 0.f;
                #pragma unroll
                for (int lane = 0; lane < 2; lane++) {
                    const int b  = bp*2 + lane;      // 0..3 within this thread
                    const int Lb = len[b];
                    const bool valid = (s < Lb);
                    float hres = lane ? hold.y : hold.x;
                    if (valid) {
                        float zi = lane ? zhi[0] : zlo[0];
                        float zj = lane ? zhi[1] : zlo[1];
                        float zf = lane ? zhi[2] : zlo[2];
                        float zo = lane ? zhi[3] : zlo[3];
                        const float4 xv = xvp[b];
                        zi += xv.x; zj += xv.y; zf += xv.z; zo += xv.w;
                        float cn = c[b]*sigmf(zf + 1.0f) + sigmf(zi)*tanhfast(zj);
                        float hn = tanhfast(cn)*sigmf(zo);
                        c[b] = cn; hres = hn;
                        const int row = bid[b]*TT + tt[b];
                        outb[(size_t)row*EE + d*HH + u] = hn;
                    }
                    if (lane == 0) hnew0 = hres; else hnew1 = hres;
                }
                hsh[wb][bpb + bp][u] = make_float2(hnew0, hnew1);
            }
        }
        __syncthreads();
    }
}

// ---------------- head: dense+relu at t=len-1, classifier, argmax ----------------
__global__ void head_kernel(const float* __restrict__ dW, const float* __restrict__ db,
                            const float* __restrict__ Wc, const float* __restrict__ bc,
                            float* __restrict__ out, int out_size)
{
    __shared__ float xs[EE];
    __shared__ float hs[HH];
    __shared__ float ls[2];
    const int b = blockIdx.x, u = threadIdx.x;
    const int t = g_lens[b] - 1;                 // lens >= 1 always
    const float* row = g_bufA + (size_t)(b*TT + t)*EE;   // final layer output lives in bufA
    for (int i = u; i < EE; i += blockDim.x) xs[i] = row[i];
    __syncthreads();
    if (u < HH) {
        float a = db[u];
        #pragma unroll 4
        for (int k = 0; k < EE; k++) a += xs[k] * dW[k*HH + u];
        hs[u] = fmaxf(a, 0.f);
    }
    __syncthreads();
    if (u < 2) {
        float a = bc[u];
        #pragma unroll 2
        for (int k = 0; k < HH; k++) a += hs[k] * Wc[k*2 + u];
        ls[u] = a;
        out[b*2 + u] = a;
    }
    __syncthreads();
    if (u == 0 && out_size >= 3*BATCH) {
        // jnp.argmax: first max wins -> strict > for class 1
        out[2*BATCH + b] = (ls[1] > ls[0]) ? 1.0f : 0.0f;
    }
}

// ---------------- launch ----------------
extern "C" void kernel_launch(void* const* d_in, const int* in_sizes, int n_in,
                              void* d_out, int out_size)
{
    (void)in_sizes; (void)n_in;
    const float* X   = (const float*)d_in[0];
    const int*   Xm  = (const int*)d_in[1];
    const float* fwk = (const float*)d_in[2];
    const float* fwb = (const float*)d_in[3];
    const float* bwk = (const float*)d_in[4];
    const float* bwb = (const float*)d_in[5];
    const float* dW  = (const float*)d_in[6];
    const float* db  = (const float*)d_in[7];
    const float* Wc  = (const float*)d_in[8];
    const float* bc  = (const float*)d_in[9];

    pack_weights<<<1024, 256>>>(fwk, fwb, bwk, bwb);
    prep_kernel<<<1, BATCH>>>(Xm);

    for (int L = 0; L < DEPTH; L++) {
        // ping-pong: L0 X->A, L1 A->B, L2 B->A, L3 A->B, L4 B->A (final in A)
        int inSel  = (L == 0) ? 0 : ((L & 1) ? 1 : 2);
        int outSel = (L & 1) ? 2 : 1;
        dim3 grid(MROWS/64, (NP + 127)/128);
        xz_gemm<<<grid, 128>>>(L, inSel, X);
        dim3 rgrid(BATCH/8, 2);
        lstm_rec<<<rgrid, 320>>>(L, outSel);
    }
    head_kernel<<<BATCH, 160>>>(dW, db, Wc, bc, (float*)d_out, out_size);
}

// round 16
// speedup vs baseline: 1.5818x; 1.5818x over previous
#include <cuda_runtime.h>

#define BATCH 1024
#define TT    70
#define EE    300      // input width per layer (E = 2H = 300)
#define HH    150
#define DEPTH 5
#define G4    600      // 4*H
#define NP    1200     // fw + bw gate-packed width
#define MROWS (BATCH*TT)

typedef unsigned long long u64;

// ---------------- device scratch (allocation-free) ----------------
__device__ float g_Wxp[DEPTH*EE*NP];      // packed x-weights  [l][k][dir*600 + u*4 + g]
__device__ float g_Whp[DEPTH*2*HH*G4];    // packed h-weights  [l][dir][k][u*4 + g]
__device__ float g_biasp[DEPTH*NP];       // packed bias
__device__ float g_xz[MROWS*NP];          // per-layer xz precompute (valid rows only)
__device__ float g_bufA[MROWS*EE];
__device__ float g_bufB[MROWS*EE];
__device__ int   g_lens[BATCH];
__device__ int   g_perm[BATCH];           // batches sorted by len desc (stable)
__device__ int   g_rows[MROWS];           // compacted valid (b,t) rows, sorted by (b,t)
__device__ int   g_nvalid;

// ---------------- f32x2 helpers ----------------
__device__ __forceinline__ u64 pack2(float x, float y) {
    u64 r; asm("mov.b64 %0, {%1, %2};" : "=l"(r) : "f"(x), "f"(y)); return r;
}
__device__ __forceinline__ void unpack2(u64 v, float& x, float& y) {
    asm("mov.b64 {%0, %1}, %2;" : "=f"(x), "=f"(y) : "l"(v));
}
__device__ __forceinline__ void fma2(u64& d, u64 a, u64 b) {
    asm("fma.rn.f32x2 %0, %1, %2, %0;" : "+l"(d) : "l"(a), "l"(b));
}

__device__ __forceinline__ float sigmf(float x) { return 1.0f / (1.0f + __expf(-x)); }
__device__ __forceinline__ float tanhfast(float x) { return 2.0f * sigmf(2.0f * x) - 1.0f; }

// ---------------- weight packing ----------------
__global__ void pack_weights(const float* __restrict__ fwk, const float* __restrict__ fwb,
                             const float* __restrict__ bwk, const float* __restrict__ bwb)
{
    int i = blockIdx.x * blockDim.x + threadIdx.x;
    int stride = gridDim.x * blockDim.x;
    // Wx part: rows 0..299 of kernel
    for (int idx = i; idx < DEPTH*EE*NP; idx += stride) {
        int l = idx / (EE*NP); int r = idx % (EE*NP);
        int k = r / NP; int cgl = r % NP;
        int dir = cgl / G4; int cc = cgl % G4;
        int u = cc >> 2; int g = cc & 3;
        const float* kk = dir ? bwk : fwk;
        g_Wxp[idx] = kk[(l*(EE+HH) + k)*G4 + u + HH*g];
    }
    // Wh part: rows 300..449 of kernel
    for (int idx = i; idx < DEPTH*2*HH*G4; idx += stride) {
        int l = idx / (2*HH*G4); int r = idx % (2*HH*G4);
        int dir = r / (HH*G4); int r2 = r % (HH*G4);
        int k = r2 / G4; int cc = r2 % G4;
        int u = cc >> 2; int g = cc & 3;
        const float* kk = dir ? bwk : fwk;
        g_Whp[idx] = kk[(l*(EE+HH) + EE + k)*G4 + u + HH*g];
    }
    for (int idx = i; idx < DEPTH*NP; idx += stride) {
        int l = idx / NP; int cgl = idx % NP;
        int dir = cgl / G4; int cc = cgl % G4;
        int u = cc >> 2; int g = cc & 3;
        g_biasp[idx] = (dir ? bwb : fwb)[l*G4 + u + HH*g];
    }
}

// ---------------- fused prep: lens + deterministic compaction + rank sort --------
__global__ void __launch_bounds__(BATCH) prep_kernel(const int* __restrict__ mask)
{
    __shared__ int lensh[BATCH];
    const int b = threadIdx.x;

    int s = 0;
    #pragma unroll
    for (int t = 0; t < TT; t++) s += mask[b*TT + t];
    g_lens[b] = s;
    lensh[b] = s;
    __syncthreads();

    const int myl = s;
    int r = 0, base = 0;
    for (int i = 0; i < BATCH; i++) {
        int lb = lensh[i];
        r += (lb > myl) || (lb == myl && i < b);
        base += (i < b) ? lb : 0;
    }
    for (int t = 0; t < myl; t++) g_rows[base + t] = b*TT + t;
    g_perm[r] = b;
    if (b == BATCH - 1) g_nvalid = base + myl;
}

// ---------------- xz precompute GEMM over VALID rows: [nvalid,300] @ [300,1200] + bias ----
__global__ void __launch_bounds__(128) xz_gemm(int layer, int inSel, const float* __restrict__ Xin)
{
    const int nvalid = g_nvalid;
    const int bm = blockIdx.x * 64;
    if (bm >= nvalid) return;

    const float* A  = (inSel == 0) ? Xin : (inSel == 1 ? g_bufA : g_bufB);
    const float* Bw = g_Wxp + layer*EE*NP;
    const float* bias = g_biasp + layer*NP;
    float* C = g_xz;

    __shared__ __align__(16) float As[12][64];
    __shared__ __align__(16) float Bs[12][128];
    __shared__ int rowid[64];

    const int bn = blockIdx.y * 128;
    const int tid = threadIdx.x;
    const int tm = (tid >> 4) << 3;   // 0..56
    const int tn = (tid & 15) << 3;   // 0..120

    if (tid < 64) {
        int r = bm + tid;
        rowid[tid] = (r < nvalid) ? g_rows[r] : -1;
    }
    __syncthreads();

    // per-thread fixed load coordinates
    int am[6], ak[6];
    const float* aptr[6];
    #pragma unroll
    for (int i = 0; i < 6; i++) {
        int idx = tid + i*128;          // 0..767
        am[i] = idx / 12; ak[i] = idx % 12;
        int rr = rowid[am[i]];
        aptr[i] = A + (size_t)(rr < 0 ? 0 : rr)*EE + ak[i];
    }
    int bk[3], bn4[3]; bool bok[3];
    #pragma unroll
    for (int i = 0; i < 3; i++) {
        int idx = tid + i*128;          // 0..383
        bk[i] = idx >> 5; bn4[i] = (idx & 31) << 2;
        bok[i] = (bn + bn4[i] < NP);
    }

    u64 acc[8][4];
    #pragma unroll
    for (int i = 0; i < 8; i++)
        #pragma unroll
        for (int j = 0; j < 4; j++) acc[i][j] = 0ull;

    // prologue: fetch tile 0 into registers
    float  pa[6];
    float4 pb[3];
    #pragma unroll
    for (int i = 0; i < 6; i++) pa[i] = __ldg(aptr[i]);
    #pragma unroll
    for (int i = 0; i < 3; i++)
        pb[i] = bok[i] ? __ldg((const float4*)&Bw[bk[i]*NP + bn + bn4[i]])
                       : make_float4(0.f, 0.f, 0.f, 0.f);

    const int NTILE = EE / 12;   // 25
    for (int tno = 0; tno < NTILE; tno++) {
        #pragma unroll
        for (int i = 0; i < 6; i++) As[ak[i]][am[i]] = pa[i];
        #pragma unroll
        for (int i = 0; i < 3; i++) *(float4*)&Bs[bk[i]][bn4[i]] = pb[i];
        __syncthreads();

        if (tno + 1 < NTILE) {
            const int k0n = (tno + 1) * 12;
            #pragma unroll
            for (int i = 0; i < 6; i++) pa[i] = __ldg(aptr[i] + k0n);
            #pragma unroll
            for (int i = 0; i < 3; i++)
                pb[i] = bok[i] ? __ldg((const float4*)&Bw[(k0n + bk[i])*NP + bn + bn4[i]])
                               : make_float4(0.f, 0.f, 0.f, 0.f);
        }

        #pragma unroll
        for (int k = 0; k < 12; k++) {
            float4 a0 = *(const float4*)&As[k][tm];
            float4 a1 = *(const float4*)&As[k][tm + 4];
            u64 a[8];
            a[0] = pack2(a0.x, a0.x); a[1] = pack2(a0.y, a0.y);
            a[2] = pack2(a0.z, a0.z); a[3] = pack2(a0.w, a0.w);
            a[4] = pack2(a1.x, a1.x); a[5] = pack2(a1.y, a1.y);
            a[6] = pack2(a1.z, a1.z); a[7] = pack2(a1.w, a1.w);
            float4 b0 = *(const float4*)&Bs[k][tn];
            float4 b1 = *(const float4*)&Bs[k][tn + 4];
            u64 bb[4];
            bb[0] = pack2(b0.x, b0.y); bb[1] = pack2(b0.z, b0.w);
            bb[2] = pack2(b1.x, b1.y); bb[3] = pack2(b1.z, b1.w);
            #pragma unroll
            for (int i = 0; i < 8; i++)
                #pragma unroll
                for (int j = 0; j < 4; j++) fma2(acc[i][j], a[i], bb[j]);
        }
        __syncthreads();
    }
    // epilogue: add bias, scatter-store to absolute rows
    #pragma unroll
    for (int i = 0; i < 8; i++) {
        int rr = rowid[tm + i];
        if (rr < 0) continue;
        float* crow = C + (size_t)rr*NP + bn + tn;
        #pragma unroll
        for (int j = 0; j < 4; j++) {
            int col = bn + tn + 2*j;
            if (col < NP) {
                float lo, hi; unpack2(acc[i][j], lo, hi);
                lo += bias[col]; hi += bias[col + 1];
                float2 v = make_float2(lo, hi);
                *(float2*)(crow + 2*j) = v;
            }
        }
    }
}

// ---------------- recurrent kernel: ONE direction per block, 16 sorted batches -----
// grid (64, 2): blockIdx.y = direction. 320 threads = batch-half(2) x unit(160).
// Each thread: 8 batches (4 pairs), all gates for its unit -> 2x arithmetic
// intensity against the same per-block 360KB weight stream. 128 blocks total
// halves chip-wide L2 weight traffic per step (was the binding constraint:
// round-14 profile showed fma=18.3%, occ=23.7% -> L2-weight-bandwidth bound);
// compute issue (~12K cyc/step) becomes the bound, and the per-block slice is
// now mostly L1-resident across steps. Register cap at 320 threads = 204
// (live ~150-170) -> spilling impossible.
__global__ void __launch_bounds__(320) lstm_rec(int layer, int outSel)
{
    const int d = blockIdx.y;
    const float* xz  = g_xz;
    const float* Whp = g_Whp + (layer*2 + d)*HH*G4;
    float* outb = (outSel == 1) ? g_bufA : g_bufB;

    // double-buffered packed h: [buf][batch-pair(8)][k], float2 = (b even, b odd)
    __shared__ __align__(16) float2 hsh[2][8][HH + 2];
    __shared__ int lensh[16];
    __shared__ int bidsh[16];

    const int tid = threadIdx.x;
    const int u   = tid % 160;
    const int bh  = tid / 160;       // 0..1 batch half
    const int bpb = bh * 4;          // pairs bpb..bpb+3
    const bool act = (u < HH);

    float c[8];
    #pragma unroll
    for (int b = 0; b < 8; b++) c[b] = 0.f;

    if (bh == 0 && act) {
        #pragma unroll
        for (int bp = 0; bp < 8; bp++) hsh[0][bp][u] = make_float2(0.f, 0.f);
    }
    if (tid < 16) {
        int bid = g_perm[blockIdx.x * 16 + tid];
        bidsh[tid] = bid;
        lensh[tid] = g_lens[bid];
    }
    __syncthreads();

    int len[8], bid[8];
    #pragma unroll
    for (int b = 0; b < 8; b++) { len[b] = lensh[bh*8 + b]; bid[b] = bidsh[bh*8 + b]; }
    int mlen = 0;
    #pragma unroll
    for (int b = 0; b < 8; b++) mlen = max(mlen, len[b]);
    const int blockMax = lensh[0];   // sorted desc

    const float* wp = Whp + u*4;
    const float* xzb[8];
    #pragma unroll
    for (int b = 0; b < 8; b++) xzb[b] = xz + (size_t)bid[b]*TT*NP + d*G4 + u*4;

    for (int s = 0; s < blockMax; s++) {
        const int rb = s & 1, wb = rb ^ 1;
        if (act && s < mlen) {
            // early xz gate prefetch: latency hides under the dot product below
            float4 xvp[8];
            int    tt[8];
            #pragma unroll
            for (int b = 0; b < 8; b++) {
                const bool v = (s < len[b]);
                const int t = (d == 0) ? s : (len[b] - 1 - s);
                tt[b] = t;
                xvp[b] = __ldg((const float4*)(xzb[b] + (size_t)(v ? t : 0)*NP));
            }

            u64 acc[4][4];
            #pragma unroll
            for (int bp = 0; bp < 4; bp++)
                #pragma unroll
                for (int g = 0; g < 4; g++) acc[bp][g] = 0ull;

            #pragma unroll 5
            for (int k = 0; k < HH; k += 2) {
                float4 w0 = __ldg((const float4*)(wp + k*G4));
                float4 w1 = __ldg((const float4*)(wp + (k+1)*G4));
                u64 wd0[4], wd1[4];
                wd0[0] = pack2(w0.x, w0.x); wd0[1] = pack2(w0.y, w0.y);
                wd0[2] = pack2(w0.z, w0.z); wd0[3] = pack2(w0.w, w0.w);
                wd1[0] = pack2(w1.x, w1.x); wd1[1] = pack2(w1.y, w1.y);
                wd1[2] = pack2(w1.z, w1.z); wd1[3] = pack2(w1.w, w1.w);
                #pragma unroll
                for (int bp = 0; bp < 4; bp++) {
                    const u64* hp = (const u64*)&hsh[rb][bpb + bp][k];
                    u64 h0 = hp[0], h1 = hp[1];
                    #pragma unroll
                    for (int g = 0; g < 4; g++) {
                        fma2(acc[bp][g], h0, wd0[g]);
                        fma2(acc[bp][g], h1, wd1[g]);
                    }
                }
            }
            // epilogue per batch pair
            #pragma unroll
            for (int bp = 0; bp < 4; bp++) {
                float zlo[4], zhi[4];
                #pragma unroll
                for (int g = 0; g < 4; g++) unpack2(acc[bp][g], zlo[g], zhi[g]);
                float2 hold = hsh[rb][bpb + bp][u];
                float hnew0 = 0.f, hnew1 = 0.f;
                #pragma unroll
                for (int lane = 0; lane < 2; lane++) {
                    const int b  = bp*2 + lane;      // 0..7 within this thread
                    const int Lb = len[b];
                    const bool valid = (s < Lb);
                    float hres = lane ? hold.y : hold.x;
                    if (valid) {
                        float zi = lane ? zhi[0] : zlo[0];
                        float zj = lane ? zhi[1] : zlo[1];
                        float zf = lane ? zhi[2] : zlo[2];
                        float zo = lane ? zhi[3] : zlo[3];
                        const float4 xv = xvp[b];
                        zi += xv.x; zj += xv.y; zf += xv.z; zo += xv.w;
                        float cn = c[b]*sigmf(zf + 1.0f) + sigmf(zi)*tanhfast(zj);
                        float hn = tanhfast(cn)*sigmf(zo);
                        c[b] = cn; hres = hn;
                        const int row = bid[b]*TT + tt[b];
                        outb[(size_t)row*EE + d*HH + u] = hn;
                    }
                    if (lane == 0) hnew0 = hres; else hnew1 = hres;
                }
                hsh[wb][bpb + bp][u] = make_float2(hnew0, hnew1);
            }
        }
        __syncthreads();
    }
}

// ---------------- head: dense+relu at t=len-1, classifier, argmax ----------------
__global__ void head_kernel(const float* __restrict__ dW, const float* __restrict__ db,
                            const float* __restrict__ Wc, const float* __restrict__ bc,
                            float* __restrict__ out, int out_size)
{
    __shared__ float xs[EE];
    __shared__ float hs[HH];
    __shared__ float ls[2];
    const int b = blockIdx.x, u = threadIdx.x;
    const int t = g_lens[b] - 1;                 // lens >= 1 always
    const float* row = g_bufA + (size_t)(b*TT + t)*EE;   // final layer output lives in bufA
    for (int i = u; i < EE; i += blockDim.x) xs[i] = row[i];
    __syncthreads();
    if (u < HH) {
        float a = db[u];
        #pragma unroll 4
        for (int k = 0; k < EE; k++) a += xs[k] * dW[k*HH + u];
        hs[u] = fmaxf(a, 0.f);
    }
    __syncthreads();
    if (u < 2) {
        float a = bc[u];
        #pragma unroll 2
        for (int k = 0; k < HH; k++) a += hs[k] * Wc[k*2 + u];
        ls[u] = a;
        out[b*2 + u] = a;
    }
    __syncthreads();
    if (u == 0 && out_size >= 3*BATCH) {
        // jnp.argmax: first max wins -> strict > for class 1
        out[2*BATCH + b] = (ls[1] > ls[0]) ? 1.0f : 0.0f;
    }
}

// ---------------- launch ----------------
extern "C" void kernel_launch(void* const* d_in, const int* in_sizes, int n_in,
                              void* d_out, int out_size)
{
    (void)in_sizes; (void)n_in;
    const float* X   = (const float*)d_in[0];
    const int*   Xm  = (const int*)d_in[1];
    const float* fwk = (const float*)d_in[2];
    const float* fwb = (const float*)d_in[3];
    const float* bwk = (const float*)d_in[4];
    const float* bwb = (const float*)d_in[5];
    const float* dW  = (const float*)d_in[6];
    const float* db  = (const float*)d_in[7];
    const float* Wc  = (const float*)d_in[8];
    const float* bc  = (const float*)d_in[9];

    pack_weights<<<1024, 256>>>(fwk, fwb, bwk, bwb);
    prep_kernel<<<1, BATCH>>>(Xm);

    for (int L = 0; L < DEPTH; L++) {
        // ping-pong: L0 X->A, L1 A->B, L2 B->A, L3 A->B, L4 B->A (final in A)
        int inSel  = (L == 0) ? 0 : ((L & 1) ? 1 : 2);
        int outSel = (L & 1) ? 2 : 1;
        dim3 grid(MROWS/64, (NP + 127)/128);
        xz_gemm<<<grid, 128>>>(L, inSel, X);
        dim3 rgrid(BATCH/16, 2);
        lstm_rec<<<rgrid, 320>>>(L, outSel);
    }
    head_kernel<<<BATCH, 160>>>(dW, db, Wc, bc, (float*)d_out, out_size);
}

// round 17
// speedup vs baseline: 1.8395x; 1.1629x over previous
#include <cuda_runtime.h>

#define BATCH 1024
#define TT    70
#define EE    300      // input width per layer (E = 2H = 300)
#define HH    150
#define DEPTH 5
#define G4    600      // 4*H
#define NP    1200     // fw + bw gate-packed width
#define MROWS (BATCH*TT)

typedef unsigned long long u64;

// ---------------- device scratch (allocation-free) ----------------
__device__ float g_Wxp[DEPTH*EE*NP];      // packed x-weights  [l][k][dir*600 + u*4 + g]
__device__ float g_Whp[DEPTH*2*HH*G4];    // packed h-weights  [l][dir][k][u*4 + g]
__device__ float g_biasp[DEPTH*NP];       // packed bias
__device__ float g_xz[MROWS*NP];          // per-layer xz precompute (valid rows only)
__device__ float g_bufA[MROWS*EE];
__device__ float g_bufB[MROWS*EE];
__device__ int   g_lens[BATCH];
__device__ int   g_perm[BATCH];           // batches sorted by len desc (stable)
__device__ int   g_rows[MROWS];           // compacted valid (b,t) rows, sorted by (b,t)
__device__ int   g_nvalid;

// ---------------- f32x2 helpers ----------------
__device__ __forceinline__ u64 pack2(float x, float y) {
    u64 r; asm("mov.b64 %0, {%1, %2};" : "=l"(r) : "f"(x), "f"(y)); return r;
}
__device__ __forceinline__ void unpack2(u64 v, float& x, float& y) {
    asm("mov.b64 {%0, %1}, %2;" : "=f"(x), "=f"(y) : "l"(v));
}
__device__ __forceinline__ void fma2(u64& d, u64 a, u64 b) {
    asm("fma.rn.f32x2 %0, %1, %2, %0;" : "+l"(d) : "l"(a), "l"(b));
}

// fast activations: 1 MUFU each via tanh.approx (sm_75+); huge margin vs 1e-3 gate
__device__ __forceinline__ float tanha(float x) {
    float y; asm("tanh.approx.f32 %0, %1;" : "=f"(y) : "f"(x)); return y;
}
__device__ __forceinline__ float sigma(float x) {
    return fmaf(tanha(0.5f * x), 0.5f, 0.5f);
}

__device__ __forceinline__ float sigmf(float x) { return 1.0f / (1.0f + __expf(-x)); }

// ---------------- weight packing ----------------
__global__ void pack_weights(const float* __restrict__ fwk, const float* __restrict__ fwb,
                             const float* __restrict__ bwk, const float* __restrict__ bwb)
{
    int i = blockIdx.x * blockDim.x + threadIdx.x;
    int stride = gridDim.x * blockDim.x;
    // Wx part: rows 0..299 of kernel
    for (int idx = i; idx < DEPTH*EE*NP; idx += stride) {
        int l = idx / (EE*NP); int r = idx % (EE*NP);
        int k = r / NP; int cgl = r % NP;
        int dir = cgl / G4; int cc = cgl % G4;
        int u = cc >> 2; int g = cc & 3;
        const float* kk = dir ? bwk : fwk;
        g_Wxp[idx] = kk[(l*(EE+HH) + k)*G4 + u + HH*g];
    }
    // Wh part: rows 300..449 of kernel
    for (int idx = i; idx < DEPTH*2*HH*G4; idx += stride) {
        int l = idx / (2*HH*G4); int r = idx % (2*HH*G4);
        int dir = r / (HH*G4); int r2 = r % (HH*G4);
        int k = r2 / G4; int cc = r2 % G4;
        int u = cc >> 2; int g = cc & 3;
        const float* kk = dir ? bwk : fwk;
        g_Whp[idx] = kk[(l*(EE+HH) + EE + k)*G4 + u + HH*g];
    }
    for (int idx = i; idx < DEPTH*NP; idx += stride) {
        int l = idx / NP; int cgl = idx % NP;
        int dir = cgl / G4; int cc = cgl % G4;
        int u = cc >> 2; int g = cc & 3;
        g_biasp[idx] = (dir ? bwb : fwb)[l*G4 + u + HH*g];
    }
}

// ---------------- fused prep: lens + deterministic compaction + rank sort --------
__global__ void __launch_bounds__(BATCH) prep_kernel(const int* __restrict__ mask)
{
    __shared__ int lensh[BATCH];
    const int b = threadIdx.x;

    int s = 0;
    #pragma unroll
    for (int t = 0; t < TT; t++) s += mask[b*TT + t];
    g_lens[b] = s;
    lensh[b] = s;
    __syncthreads();

    const int myl = s;
    int r = 0, base = 0;
    for (int i = 0; i < BATCH; i++) {
        int lb = lensh[i];
        r += (lb > myl) || (lb == myl && i < b);
        base += (i < b) ? lb : 0;
    }
    for (int t = 0; t < myl; t++) g_rows[base + t] = b*TT + t;
    g_perm[r] = b;
    if (b == BATCH - 1) g_nvalid = base + myl;
}

// ---------------- xz precompute GEMM over VALID rows: [nvalid,300] @ [300,1200] + bias ----
__global__ void __launch_bounds__(128) xz_gemm(int layer, int inSel, const float* __restrict__ Xin)
{
    const int nvalid = g_nvalid;
    const int bm = blockIdx.x * 64;
    if (bm >= nvalid) return;

    const float* A  = (inSel == 0) ? Xin : (inSel == 1 ? g_bufA : g_bufB);
    const float* Bw = g_Wxp + layer*EE*NP;
    const float* bias = g_biasp + layer*NP;
    float* C = g_xz;

    __shared__ __align__(16) float As[12][64];
    __shared__ __align__(16) float Bs[12][128];
    __shared__ int rowid[64];

    const int bn = blockIdx.y * 128;
    const int tid = threadIdx.x;
    const int tm = (tid >> 4) << 3;   // 0..56
    const int tn = (tid & 15) << 3;   // 0..120

    if (tid < 64) {
        int r = bm + tid;
        rowid[tid] = (r < nvalid) ? g_rows[r] : -1;
    }
    __syncthreads();

    // per-thread fixed load coordinates
    int am[6], ak[6];
    const float* aptr[6];
    #pragma unroll
    for (int i = 0; i < 6; i++) {
        int idx = tid + i*128;          // 0..767
        am[i] = idx / 12; ak[i] = idx % 12;
        int rr = rowid[am[i]];
        aptr[i] = A + (size_t)(rr < 0 ? 0 : rr)*EE + ak[i];
    }
    int bk[3], bn4[3]; bool bok[3];
    #pragma unroll
    for (int i = 0; i < 3; i++) {
        int idx = tid + i*128;          // 0..383
        bk[i] = idx >> 5; bn4[i] = (idx & 31) << 2;
        bok[i] = (bn + bn4[i] < NP);
    }

    u64 acc[8][4];
    #pragma unroll
    for (int i = 0; i < 8; i++)
        #pragma unroll
        for (int j = 0; j < 4; j++) acc[i][j] = 0ull;

    // prologue: fetch tile 0 into registers
    float  pa[6];
    float4 pb[3];
    #pragma unroll
    for (int i = 0; i < 6; i++) pa[i] = __ldg(aptr[i]);
    #pragma unroll
    for (int i = 0; i < 3; i++)
        pb[i] = bok[i] ? __ldg((const float4*)&Bw[bk[i]*NP + bn + bn4[i]])
                       : make_float4(0.f, 0.f, 0.f, 0.f);

    const int NTILE = EE / 12;   // 25
    for (int tno = 0; tno < NTILE; tno++) {
        #pragma unroll
        for (int i = 0; i < 6; i++) As[ak[i]][am[i]] = pa[i];
        #pragma unroll
        for (int i = 0; i < 3; i++) *(float4*)&Bs[bk[i]][bn4[i]] = pb[i];
        __syncthreads();

        if (tno + 1 < NTILE) {
            const int k0n = (tno + 1) * 12;
            #pragma unroll
            for (int i = 0; i < 6; i++) pa[i] = __ldg(aptr[i] + k0n);
            #pragma unroll
            for (int i = 0; i < 3; i++)
                pb[i] = bok[i] ? __ldg((const float4*)&Bw[(k0n + bk[i])*NP + bn + bn4[i]])
                               : make_float4(0.f, 0.f, 0.f, 0.f);
        }

        #pragma unroll
        for (int k = 0; k < 12; k++) {
            float4 a0 = *(const float4*)&As[k][tm];
            float4 a1 = *(const float4*)&As[k][tm + 4];
            u64 a[8];
            a[0] = pack2(a0.x, a0.x); a[1] = pack2(a0.y, a0.y);
            a[2] = pack2(a0.z, a0.z); a[3] = pack2(a0.w, a0.w);
            a[4] = pack2(a1.x, a1.x); a[5] = pack2(a1.y, a1.y);
            a[6] = pack2(a1.z, a1.z); a[7] = pack2(a1.w, a1.w);
            float4 b0 = *(const float4*)&Bs[k][tn];
            float4 b1 = *(const float4*)&Bs[k][tn + 4];
            u64 bb[4];
            bb[0] = pack2(b0.x, b0.y); bb[1] = pack2(b0.z, b0.w);
            bb[2] = pack2(b1.x, b1.y); bb[3] = pack2(b1.z, b1.w);
            #pragma unroll
            for (int i = 0; i < 8; i++)
                #pragma unroll
                for (int j = 0; j < 4; j++) fma2(acc[i][j], a[i], bb[j]);
        }
        __syncthreads();
    }
    // epilogue: add bias, scatter-store to absolute rows
    #pragma unroll
    for (int i = 0; i < 8; i++) {
        int rr = rowid[tm + i];
        if (rr < 0) continue;
        float* crow = C + (size_t)rr*NP + bn + tn;
        #pragma unroll
        for (int j = 0; j < 4; j++) {
            int col = bn + tn + 2*j;
            if (col < NP) {
                float lo, hi; unpack2(acc[i][j], lo, hi);
                lo += bias[col]; hi += bias[col + 1];
                float2 v = make_float2(lo, hi);
                *(float2*)(crow + 2*j) = v;
            }
        }
    }
}

// ---------------- recurrent kernel: ONE direction per block, 16 sorted batches -----
// grid (64, 2). 320 threads = batch-half(2) x unit-slot(160); 8 batches/thread.
// Weight-L2-traffic structure validated over two rounds (14->16: 1.69->1.06 ms).
// This round: epilogue activations via tanh.approx (1 MUFU) + sigmoid-from-tanh
// (1 MUFU + 1 FMA) -> MUFU count per step drops ~2.2x and the post-dot-product
// serial chain shortens; matters because only 2.5 warps/SMSP cover latency.
__global__ void __launch_bounds__(320) lstm_rec(int layer, int outSel)
{
    const int d = blockIdx.y;
    const float* xz  = g_xz;
    const float* Whp = g_Whp + (layer*2 + d)*HH*G4;
    float* outb = (outSel == 1) ? g_bufA : g_bufB;

    // double-buffered packed h: [buf][batch-pair(8)][k], float2 = (b even, b odd)
    __shared__ __align__(16) float2 hsh[2][8][HH + 2];
    __shared__ int lensh[16];
    __shared__ int bidsh[16];

    const int tid = threadIdx.x;
    const int u   = tid % 160;
    const int bh  = tid / 160;       // 0..1 batch half
    const int bpb = bh * 4;          // pairs bpb..bpb+3
    const bool act = (u < HH);

    float c[8];
    #pragma unroll
    for (int b = 0; b < 8; b++) c[b] = 0.f;

    if (bh == 0 && act) {
        #pragma unroll
        for (int bp = 0; bp < 8; bp++) hsh[0][bp][u] = make_float2(0.f, 0.f);
    }
    if (tid < 16) {
        int bid = g_perm[blockIdx.x * 16 + tid];
        bidsh[tid] = bid;
        lensh[tid] = g_lens[bid];
    }
    __syncthreads();

    int len[8], bid[8];
    #pragma unroll
    for (int b = 0; b < 8; b++) { len[b] = lensh[bh*8 + b]; bid[b] = bidsh[bh*8 + b]; }
    int mlen = 0;
    #pragma unroll
    for (int b = 0; b < 8; b++) mlen = max(mlen, len[b]);
    const int blockMax = lensh[0];   // sorted desc

    const float* wp = Whp + u*4;
    const float* xzb[8];
    #pragma unroll
    for (int b = 0; b < 8; b++) xzb[b] = xz + (size_t)bid[b]*TT*NP + d*G4 + u*4;

    for (int s = 0; s < blockMax; s++) {
        const int rb = s & 1, wb = rb ^ 1;
        if (act && s < mlen) {
            // early xz gate prefetch: latency hides under the dot product below
            float4 xvp[8];
            int    tt[8];
            #pragma unroll
            for (int b = 0; b < 8; b++) {
                const bool v = (s < len[b]);
                const int t = (d == 0) ? s : (len[b] - 1 - s);
                tt[b] = t;
                xvp[b] = __ldg((const float4*)(xzb[b] + (size_t)(v ? t : 0)*NP));
            }

            u64 acc[4][4];
            #pragma unroll
            for (int bp = 0; bp < 4; bp++)
                #pragma unroll
                for (int g = 0; g < 4; g++) acc[bp][g] = 0ull;

            #pragma unroll 5
            for (int k = 0; k < HH; k += 2) {
                float4 w0 = __ldg((const float4*)(wp + k*G4));
                float4 w1 = __ldg((const float4*)(wp + (k+1)*G4));
                u64 wd0[4], wd1[4];
                wd0[0] = pack2(w0.x, w0.x); wd0[1] = pack2(w0.y, w0.y);
                wd0[2] = pack2(w0.z, w0.z); wd0[3] = pack2(w0.w, w0.w);
                wd1[0] = pack2(w1.x, w1.x); wd1[1] = pack2(w1.y, w1.y);
                wd1[2] = pack2(w1.z, w1.z); wd1[3] = pack2(w1.w, w1.w);
                #pragma unroll
                for (int bp = 0; bp < 4; bp++) {
                    const u64* hp = (const u64*)&hsh[rb][bpb + bp][k];
                    u64 h0 = hp[0], h1 = hp[1];
                    #pragma unroll
                    for (int g = 0; g < 4; g++) {
                        fma2(acc[bp][g], h0, wd0[g]);
                        fma2(acc[bp][g], h1, wd1[g]);
                    }
                }
            }
            // epilogue per batch pair
            #pragma unroll
            for (int bp = 0; bp < 4; bp++) {
                float zlo[4], zhi[4];
                #pragma unroll
                for (int g = 0; g < 4; g++) unpack2(acc[bp][g], zlo[g], zhi[g]);
                float2 hold = hsh[rb][bpb + bp][u];
                float hnew0 = 0.f, hnew1 = 0.f;
                #pragma unroll
                for (int lane = 0; lane < 2; lane++) {
                    const int b  = bp*2 + lane;      // 0..7 within this thread
                    const int Lb = len[b];
                    const bool valid = (s < Lb);
                    float hres = lane ? hold.y : hold.x;
                    if (valid) {
                        float zi = lane ? zhi[0] : zlo[0];
                        float zj = lane ? zhi[1] : zlo[1];
                        float zf = lane ? zhi[2] : zlo[2];
                        float zo = lane ? zhi[3] : zlo[3];
                        const float4 xv = xvp[b];
                        zi += xv.x; zj += xv.y; zf += xv.z; zo += xv.w;
                        float cn = c[b]*sigma(zf + 1.0f) + sigma(zi)*tanha(zj);
                        float hn = tanha(cn)*sigma(zo);
                        c[b] = cn; hres = hn;
                        const int row = bid[b]*TT + tt[b];
                        outb[(size_t)row*EE + d*HH + u] = hn;
                    }
                    if (lane == 0) hnew0 = hres; else hnew1 = hres;
                }
                hsh[wb][bpb + bp][u] = make_float2(hnew0, hnew1);
            }
        }
        __syncthreads();
    }
}

// ---------------- head: dense+relu at t=len-1, classifier, argmax ----------------
__global__ void head_kernel(const float* __restrict__ dW, const float* __restrict__ db,
                            const float* __restrict__ Wc, const float* __restrict__ bc,
                            float* __restrict__ out, int out_size)
{
    __shared__ float xs[EE];
    __shared__ float hs[HH];
    __shared__ float ls[2];
    const int b = blockIdx.x, u = threadIdx.x;
    const int t = g_lens[b] - 1;                 // lens >= 1 always
    const float* row = g_bufA + (size_t)(b*TT + t)*EE;   // final layer output lives in bufA
    for (int i = u; i < EE; i += blockDim.x) xs[i] = row[i];
    __syncthreads();
    if (u < HH) {
        float a = db[u];
        #pragma unroll 4
        for (int k = 0; k < EE; k++) a += xs[k] * dW[k*HH + u];
        hs[u] = fmaxf(a, 0.f);
    }
    __syncthreads();
    if (u < 2) {
        float a = bc[u];
        #pragma unroll 2
        for (int k = 0; k < HH; k++) a += hs[k] * Wc[k*2 + u];
        ls[u] = a;
        out[b*2 + u] = a;
    }
    __syncthreads();
    if (u == 0 && out_size >= 3*BATCH) {
        // jnp.argmax: first max wins -> strict > for class 1
        out[2*BATCH + b] = (ls[1] > ls[0]) ? 1.0f : 0.0f;
    }
}

// ---------------- launch ----------------
extern "C" void kernel_launch(void* const* d_in, const int* in_sizes, int n_in,
                              void* d_out, int out_size)
{
    (void)in_sizes; (void)n_in;
    const float* X   = (const float*)d_in[0];
    const int*   Xm  = (const int*)d_in[1];
    const float* fwk = (const float*)d_in[2];
    const float* fwb = (const float*)d_in[3];
    const float* bwk = (const float*)d_in[4];
    const float* bwb = (const float*)d_in[5];
    const float* dW  = (const float*)d_in[6];
    const float* db  = (const float*)d_in[7];
    const float* Wc  = (const float*)d_in[8];
    const float* bc  = (const float*)d_in[9];

    pack_weights<<<1024, 256>>>(fwk, fwb, bwk, bwb);
    prep_kernel<<<1, BATCH>>>(Xm);

    for (int L = 0; L < DEPTH; L++) {
        // ping-pong: L0 X->A, L1 A->B, L2 B->A, L3 A->B, L4 B->A (final in A)
        int inSel  = (L == 0) ? 0 : ((L & 1) ? 1 : 2);
        int outSel = (L & 1) ? 2 : 1;
        dim3 grid(MROWS/64, (NP + 127)/128);
        xz_gemm<<<grid, 128>>>(L, inSel, X);
        dim3 rgrid(BATCH/16, 2);
        lstm_rec<<<rgrid, 320>>>(L, outSel);
    }
    head_kernel<<<BATCH, 160>>>(dW, db, Wc, bc, (float*)d_out, out_size);
}